// round 17
// baseline (speedup 1.0000x reference)
#include <cuda_runtime.h>
#include <cuda_fp16.h>
#include <stdint.h>

// bg: (1, 4, 32, 32, 32, 16) float32  -> d_in[0]
// gm: (1, 1, 128, 128, 128) float32   -> d_in[1]
// out: (1, 4, 128, 128, 128) float32

#define G  128
#define NVOX (G * G * G)                 // 2,097,152
#define BG_SPATIAL (32 * 32 * 32 * 16)   // 524,288

// Plain fp16 channel-last grid: entry (x,y,z,t) = 8B {4 x fp16}. 4.2 MB.
__device__ uint2 g_bgH[BG_SPATIAL];

// ---------------------------------------------------------------------------
// Kernel 1: transpose (c,x,y,z,t) -> channel-last fp16x4.
// ---------------------------------------------------------------------------
__global__ void bgT_half_kernel(const float* __restrict__ bg) {
    int idx = blockIdx.x * blockDim.x + threadIdx.x;
    if (idx >= BG_SPATIAL) return;
    float a = __ldg(&bg[0 * BG_SPATIAL + idx]);
    float b = __ldg(&bg[1 * BG_SPATIAL + idx]);
    float c = __ldg(&bg[2 * BG_SPATIAL + idx]);
    float d = __ldg(&bg[3 * BG_SPATIAL + idx]);
    __half2 lo = __floats2half2_rn(a, b);
    __half2 hi = __floats2half2_rn(c, d);
    uint2 e;
    e.x = *reinterpret_cast<uint32_t*>(&lo);
    e.y = *reinterpret_cast<uint32_t*>(&hi);
    g_bgH[idx] = e;
}

// ---------------------------------------------------------------------------
// Kernel 2: slice. Tile = 4(gh) x 16(gw) x 32(gd) = 2048 voxels, 512 threads,
// 4 consecutive gd per thread (float4 gm load, STG.128 stores).
// Fill: 4 gh rows share <=3 source x-planes; each fill unit (yz-cell, t-pair)
// reads the 3 planes once (3 x LDG.128) and emits 4 x-lerped rows (STS.128).
// smem rows: [xr(4)][cy(6)][cz(10)] x 18 slots of 8B (16 t + 2 zero pad).
// Gather corner = 2 x LDS.64 (t0, t0+1), HFMA2 into half2 A/C planes,
// final r = A + ft*(C-A) in fp32. __launch_bounds__(512,4) -> 32 regs,
// 4 blocks/SM for full occupancy.
// ---------------------------------------------------------------------------
#define CY 6
#define CZ 10
#define ZS 18                    // slots per row (16 t + 2 pad), even
#define YS (CZ * ZS)             // 180
#define XS (CY * YS)             // 1080
#define NROW (4 * CY * CZ)       // 240 rows
#define NSLOT (NROW * ZS)        // 4320 slots = 34560 B
#define NUNIT (CY * CZ * 8)      // 480 fill units

__global__ __launch_bounds__(512, 4)
void bgrid_slice_kernel(const float* __restrict__ gm, float* __restrict__ out) {
    __shared__ uint2    sgrid[NSLOT];     // 34560 B
    __shared__ int      sOffZ[32], sDZ[32];
    __shared__ float    sFz[32];
    __shared__ int      sOffY[16], sDY[16];
    __shared__ uint32_t sFyh[16];         // half2(fy,fy)
    __shared__ int      sPl0[4], sPl1[4];
    __shared__ uint32_t sFxh[4];          // half2(fx,fx)

    int tid = threadIdx.x;
    int bd = blockIdx.x & 3;            // 4 gd tiles of 32
    int bw = (blockIdx.x >> 2) & 7;     // 8 gw tiles of 16
    int bh = blockIdx.x >> 5;           // 32 gh tiles of 4

    int gh0 = bh << 2, gw0 = bw << 4, gd0 = bd << 5;

    const float s = 31.0f / 127.0f;
    int bx0 = (int)floorf((float)gh0 * s);
    int by0 = (int)floorf((float)gw0 * s);
    int bz0 = (int)floorf((float)gd0 * s);

    // ---- axis LUTs (52 threads) ----
    if (tid < 52) {
        if (tid < 32) {                 // z axis (32 gd)
            float v = fminf(fmaxf((float)(gd0 + tid) * s, 0.0f), 31.0f);
            int i0 = (int)floorf(v);
            int i1 = min(i0 + 1, 31);
            sOffZ[tid] = (i0 - bz0) * ZS;
            sDZ[tid]   = (i1 - i0) * ZS;
            sFz[tid]   = v - (float)i0;
        } else if (tid < 48) {          // y axis (16 gw)
            int l = tid - 32;
            float v = fminf(fmaxf((float)(gw0 + l) * s, 0.0f), 31.0f);
            int i0 = (int)floorf(v);
            int i1 = min(i0 + 1, 31);
            sOffY[l] = (i0 - by0) * YS;
            sDY[l]   = (i1 - i0) * YS;
            float fy = v - (float)i0;
            __half2 h2 = __half2half2(__float2half_rn(fy));
            sFyh[l] = *reinterpret_cast<uint32_t*>(&h2);
        } else {                        // x rows (4 gh)
            int xr = tid - 48;
            float v = fminf(fmaxf((float)(gh0 + xr) * s, 0.0f), 31.0f);
            int i0 = (int)floorf(v);
            int i1 = min(i0 + 1, 31);
            sPl0[xr] = i0 - bx0;        // 0 or 1
            sPl1[xr] = i1 - bx0;        // 0, 1 or 2
            float fx = v - (float)i0;
            __half2 h2 = __half2half2(__float2half_rn(fx));
            sFxh[xr] = *reinterpret_cast<uint32_t*>(&h2);
        }
    }
    // ---- zero pad slots 16,17 of each row (480 stores) ----
    if (tid < 2 * NROW) {
        uint2 z; z.x = 0u; z.y = 0u;
        sgrid[(tid >> 1) * ZS + 16 + (tid & 1)] = z;
    }
    __syncthreads();

    // ---- fill: 480 units, one pass. 3 LDG.128 + 4 x (lerp + STS.128) ----
    const uint4* __restrict__ bgH4 = reinterpret_cast<const uint4*>(g_bgH);
    if (tid < NUNIT) {
        int tp   = tid & 7;             // t pair: t = 2*tp
        int cell = tid >> 3;            // cy*CZ + cz  (0..59)
        int cz   = cell % CZ;
        int cy   = cell / CZ;
        int y = min(by0 + cy, 31);
        int z = min(bz0 + cz, 31);
        int base = (y * 32 + z) * 8 + tp;     // uint4 units within an x-plane

        int xs1 = min(bx0 + 1, 31);
        int xs2 = min(bx0 + 2, 31);
        uint4 s0 = bgH4[bx0 * (32 * 32 * 8) + base];
        uint4 s1 = bgH4[xs1 * (32 * 32 * 8) + base];
        uint4 s2 = bgH4[xs2 * (32 * 32 * 8) + base];

#pragma unroll
        for (int xr = 0; xr < 4; xr++) {
            int pl0 = sPl0[xr];
            int pl1 = sPl1[xr];
            uint4 a = (pl0 == 0) ? s0 : s1;
            uint4 b = (pl1 == 0) ? s0 : ((pl1 == 1) ? s1 : s2);
            uint32_t fxu = sFxh[xr];
            __half2 fx2 = *reinterpret_cast<__half2*>(&fxu);
            uint4 r;
            {
                __half2 av = *reinterpret_cast<__half2*>(&a.x);
                __half2 bv = *reinterpret_cast<__half2*>(&b.x);
                __half2 m = __hfma2(fx2, __hsub2(bv, av), av);
                r.x = *reinterpret_cast<uint32_t*>(&m);
            }
            {
                __half2 av = *reinterpret_cast<__half2*>(&a.y);
                __half2 bv = *reinterpret_cast<__half2*>(&b.y);
                __half2 m = __hfma2(fx2, __hsub2(bv, av), av);
                r.y = *reinterpret_cast<uint32_t*>(&m);
            }
            {
                __half2 av = *reinterpret_cast<__half2*>(&a.z);
                __half2 bv = *reinterpret_cast<__half2*>(&b.z);
                __half2 m = __hfma2(fx2, __hsub2(bv, av), av);
                r.z = *reinterpret_cast<uint32_t*>(&m);
            }
            {
                __half2 av = *reinterpret_cast<__half2*>(&a.w);
                __half2 bv = *reinterpret_cast<__half2*>(&b.w);
                __half2 m = __hfma2(fx2, __hsub2(bv, av), av);
                r.w = *reinterpret_cast<uint32_t*>(&m);
            }
            int row = (xr * CY + cy) * CZ + cz;
            *reinterpret_cast<uint4*>(&sgrid[row * ZS + (tp << 1)]) = r;
        }
    }
    __syncthreads();

    // ---- gather: thread = (gdq 0..7, lw 0..15, xr 0..3), 4 consecutive gd ----
    int gdq = tid & 7;
    int lw  = (tid >> 3) & 15;
    int xr  = tid >> 7;

    int offY = sOffY[lw], dY = sDY[lw];
    uint32_t fyu = sFyh[lw];
    __half2 hy1 = *reinterpret_cast<__half2*>(&fyu);
    __half2 one2 = __float2half2_rn(1.0f);
    __half2 hy0 = __hsub2(one2, hy1);

    int gdb = gdq << 2;                    // gd base within tile
    int idx0 = ((gh0 + xr) << 14) | ((gw0 + lw) << 7) | (gd0 + gdb);

    // gm: one float4 covers the 4 voxels
    float4 g4 = __ldg(reinterpret_cast<const float4*>(gm + idx0));
    float gv[4] = { g4.x, g4.y, g4.z, g4.w };

    int bxy = xr * XS + offY;

    float4 R0, R1, R2, R3;
    float* r0 = &R0.x; float* r1 = &R1.x; float* r2 = &R2.x; float* r3 = &R3.x;

#pragma unroll
    for (int j = 0; j < 4; j++) {
        int ldz = gdb + j;
        int offZ = sOffZ[ldz], dZ = sDZ[ldz];
        __half2 hz1 = __half2half2(__float2half_rn(sFz[ldz]));
        __half2 hz0 = __hsub2(one2, hz1);

        float t = fminf(fmaxf(gv[j] * 15.0f, 0.0f), 15.0f);
        int t0 = (int)floorf(t);
        float ft = t - (float)t0;

        int b = bxy + offZ + t0;
        const int cofs[4] = { b, b + dZ, b + dY, b + dY + dZ };
        // corner weights in half2: hy{0,1} * hz{0,1}
        const __half2 wh[4] = { __hmul2(hy0, hz0), __hmul2(hy0, hz1),
                                __hmul2(hy1, hz0), __hmul2(hy1, hz1) };

        __half2 Alo = __float2half2_rn(0.0f), Ahi = Alo, Clo = Alo, Chi = Alo;
#pragma unroll
        for (int k = 0; k < 4; k++) {
            uint2 m0 = sgrid[cofs[k]];
            uint2 m1 = sgrid[cofs[k] + 1];
            Alo = __hfma2(wh[k], *reinterpret_cast<__half2*>(&m0.x), Alo);
            Ahi = __hfma2(wh[k], *reinterpret_cast<__half2*>(&m0.y), Ahi);
            Clo = __hfma2(wh[k], *reinterpret_cast<__half2*>(&m1.x), Clo);
            Chi = __hfma2(wh[k], *reinterpret_cast<__half2*>(&m1.y), Chi);
        }

        float2 alo = __half22float2(Alo);
        float2 ahi = __half22float2(Ahi);
        float2 clo = __half22float2(Clo);
        float2 chi = __half22float2(Chi);

        r0[j] = alo.x + ft * (clo.x - alo.x);
        r1[j] = alo.y + ft * (clo.y - alo.y);
        r2[j] = ahi.x + ft * (chi.x - ahi.x);
        r3[j] = ahi.y + ft * (chi.y - ahi.y);
    }

    // coalesced STG.128 per channel
    *reinterpret_cast<float4*>(out + idx0)            = R0;
    *reinterpret_cast<float4*>(out + idx0 + NVOX)     = R1;
    *reinterpret_cast<float4*>(out + idx0 + 2 * NVOX) = R2;
    *reinterpret_cast<float4*>(out + idx0 + 3 * NVOX) = R3;
}

extern "C" void kernel_launch(void* const* d_in, const int* in_sizes, int n_in,
                              void* d_out, int out_size) {
    const float* bg = (const float*)d_in[0];
    const float* gm = (const float*)d_in[1];
    float* out = (float*)d_out;

    (void)in_sizes; (void)n_in; (void)out_size;

    bgT_half_kernel<<<(BG_SPATIAL + 255) / 256, 256>>>(bg);
    bgrid_slice_kernel<<<1024, 512>>>(gm, out);
}